// round 16
// baseline (speedup 1.0000x reference)
#include <cuda_runtime.h>
#include <cuda_fp16.h>
#include <cstdint>

#define N_NODES 100000
#define N_EDGES 800000
#define F_IN    256
#define HID     128
#define CLS     32
#define SCAN_B  512
#define N_SBLK  ((N_NODES + SCAN_B - 1) / SCAN_B)   // 196

// ---------------- scratch (device globals: no allocation allowed) ----------
__device__ int    g_cnt[N_NODES];
__device__ float  g_dinv[N_NODES];
__device__ int    g_rowptr[N_NODES + 1];
__device__ int    g_cursor[N_NODES];
__device__ int    g_col[N_EDGES];
__device__ int    g_bsum[N_SBLK];
__device__ int    g_boff[N_SBLK];
__device__ __half g_q1h[(size_t)N_NODES * HID];   // raw xw1, fp16
__device__ __half g_h1h[(size_t)N_NODES * HID];   // relu output, fp16
__device__ __half g_q2h[(size_t)N_NODES * CLS];   // xw2*dinv, fp16
__device__ __half g_w1h[F_IN * HID];              // W1 fp16 hi
__device__ __half g_w1l[F_IN * HID];              // W1 fp16 lo
__device__ __half g_w2h[HID * CLS];
__device__ __half g_w2l[HID * CLS];
__device__ int    g_is64;

// ---------------- stream/events for fork-join overlap (created at load) -----
static cudaStream_t g_s2 = nullptr;
static cudaEvent_t  g_e0 = nullptr, g_e2 = nullptr;
namespace {
struct HxStreamInit {
    HxStreamInit() {
        cudaStreamCreateWithFlags(&g_s2, cudaStreamNonBlocking);
        cudaEventCreateWithFlags(&g_e0, cudaEventDisableTiming);
        cudaEventCreateWithFlags(&g_e2, cudaEventDisableTiming);
    }
};
static HxStreamInit g_hx_stream_init;
}

// ---------------- helpers ----------------------------------------------------
__device__ __forceinline__ uint32_t smem_addr(const void* p) {
    return (uint32_t)__cvta_generic_to_shared(p);
}
#define LDSM_X4(r, a)                                                          \
    asm volatile("ldmatrix.sync.aligned.m8n8.x4.shared.b16 {%0,%1,%2,%3}, [%4];" \
                 : "=r"((r)[0]), "=r"((r)[1]), "=r"((r)[2]), "=r"((r)[3])      \
                 : "r"(a))
#define LDSM_X2T(r, a)                                                         \
    asm volatile("ldmatrix.sync.aligned.m8n8.x2.trans.shared.b16 {%0,%1}, [%2];" \
                 : "=r"((r)[0]), "=r"((r)[1]) : "r"(a))
#define MMA_F16(c, a, b)                                                       \
    asm volatile("mma.sync.aligned.m16n8k16.row.col.f32.f16.f16.f32 "          \
                 "{%0,%1,%2,%3}, {%4,%5,%6,%7}, {%8,%9}, {%0,%1,%2,%3};"       \
                 : "+f"((c)[0]), "+f"((c)[1]), "+f"((c)[2]), "+f"((c)[3])      \
                 : "r"((a)[0]), "r"((a)[1]), "r"((a)[2]), "r"((a)[3]),         \
                   "r"((b)[0]), "r"((b)[1]))
#define CP_ASYNC16(dst, src, sz)                                               \
    asm volatile("cp.async.ca.shared.global [%0], [%1], 16, %2;"               \
                 :: "r"(dst), "l"(src), "r"(sz) : "memory")
#define CP_COMMIT() asm volatile("cp.async.commit_group;" ::: "memory")
#define CP_WAIT0()  asm volatile("cp.async.wait_group 0;" ::: "memory")

__device__ __forceinline__ int edge_at(const int* __restrict__ ei,
                                       int which, int e, int is64) {
    size_t base = (size_t)which * N_EDGES + (size_t)e;
    return is64 ? ei[base * 2] : ei[base];
}

// ---------------- fused init: W1/W2 fp16-split + cnt zero + dtype probe -----
__global__ void k_init(const float* __restrict__ W1,
                       const float* __restrict__ W2,
                       const int* __restrict__ ei) {
    int i = blockIdx.x * blockDim.x + threadIdx.x;
    if (i < F_IN * HID) {
        float x = W1[i];
        __half h = __float2half_rn(x);
        g_w1h[i] = h;
        g_w1l[i] = __float2half_rn(x - __half2float(h));
    }
    if (i < HID * CLS) {
        float x = W2[i];
        __half h = __float2half_rn(x);
        g_w2h[i] = h;
        g_w2l[i] = __float2half_rn(x - __half2float(h));
    }
    if (i < N_NODES) g_cnt[i] = 0;
    if (i == 0) {
        int is64 = 1;
        for (int j = 0; j < 64; j++)
            if (ei[2 * j + 1] != 0) { is64 = 0; break; }
        g_is64 = is64;
    }
}

// ---------------- degree count ----------------------------------------------
__global__ void k_cnt_scatter(const int* __restrict__ ei) {
    int e = blockIdx.x * blockDim.x + threadIdx.x;
    if (e >= N_EDGES) return;
    atomicAdd(&g_cnt[edge_at(ei, 1, e, g_is64)], 1);
}

// ---------------- CSR build: 3-phase scan (+dinv fused) + fill --------------
__global__ void k_scan1() {
    __shared__ int sh[SCAN_B];
    int t = threadIdx.x;
    int i = blockIdx.x * SCAN_B + t;
    int v = (i < N_NODES) ? g_cnt[i] : 0;
    sh[t] = v;
    __syncthreads();
#pragma unroll
    for (int off = 1; off < SCAN_B; off <<= 1) {
        int x = (t >= off) ? sh[t - off] : 0;
        __syncthreads();
        sh[t] += x;
        __syncthreads();
    }
    if (i < N_NODES) g_rowptr[i] = sh[t] - v;
    if (t == SCAN_B - 1) g_bsum[blockIdx.x] = sh[t];
}
__global__ void k_scan2() {
    __shared__ int sh[256];
    int t = threadIdx.x;
    int v = (t < N_SBLK) ? g_bsum[t] : 0;
    sh[t] = v;
    __syncthreads();
#pragma unroll
    for (int off = 1; off < 256; off <<= 1) {
        int x = (t >= off) ? sh[t - off] : 0;
        __syncthreads();
        sh[t] += x;
        __syncthreads();
    }
    if (t < N_SBLK) g_boff[t] = sh[t] - v;
}
__global__ void k_scan3() {
    int i = blockIdx.x * blockDim.x + threadIdx.x;
    if (i < N_NODES) {
        int rp = g_rowptr[i] + g_boff[i / SCAN_B];
        g_rowptr[i] = rp;
        g_cursor[i] = rp;
        g_dinv[i]   = rsqrtf((float)(g_cnt[i] + 1));   // +1 self loop
    }
    if (i == 0) g_rowptr[N_NODES] = N_EDGES;
}
__global__ void k_fill(const int* __restrict__ ei) {
    int e = blockIdx.x * blockDim.x + threadIdx.x;
    if (e >= N_EDGES) return;
    int is64 = g_is64;
    int s = edge_at(ei, 0, e, is64);
    int d = edge_at(ei, 1, e, is64);
    int pos = atomicAdd(&g_cursor[d], 1);
    g_col[pos] = s;
}

// ---------------- layer-1 GEMM: fp16 A + fp16-split W1, 2xMMA, cp.async -----
// q1h = fp16(X @ W1)
#define BM 64
#define BK 32
#define NKC (F_IN / BK)        // 8
#define A_STR 40               // halves
#define B_STR 136
#define A_BUF (BM * A_STR)     // 2560
#define B_BUF (BK * B_STR)     // 4352
#define OFF_A  0
#define OFF_BH (2 * A_BUF)
#define OFF_BL (2 * A_BUF + 2 * B_BUF)
#define SMEM_G1_ELEMS (2 * A_BUF + 4 * B_BUF)   // 22528 halves
#define SMEM_G1_BYTES (SMEM_G1_ELEMS * 2)       // 45056 B

__global__ __launch_bounds__(256, 2) void gemm1_mma(const float* __restrict__ X) {
    extern __shared__ __align__(16) char dsm_raw[];
    __half* sm = (__half*)dsm_raw;

    const int tid  = threadIdx.x;
    const int lane = tid & 31;
    const int wid  = tid >> 5;
    const int wm   = wid >> 2;       // 0..1 (32 rows)
    const int wn   = wid & 3;        // 0..3 (32 cols)
    const int rowBase = blockIdx.x * BM;

    const int a_r0 = tid >> 3,  a_c4 = (tid & 7) * 4;
    const int b_k0 = tid >> 4,  b_n8 = (tid & 15) * 8;

    float4 stA[2];

    float acc[2][4][4];
#pragma unroll
    for (int mi = 0; mi < 2; mi++)
#pragma unroll
        for (int ni = 0; ni < 4; ni++)
#pragma unroll
            for (int r = 0; r < 4; r++) acc[mi][ni][r] = 0.f;

    auto issue_B = [&](int kt, int buf) {
#pragma unroll
        for (int i = 0; i < 2; i++) {
            int k = b_k0 + i * 16;
            size_t off = (size_t)(kt + k) * HID + b_n8;
            CP_ASYNC16(smem_addr(&sm[OFF_BH + buf * B_BUF + k * B_STR + b_n8]),
                       g_w1h + off, 16);
            CP_ASYNC16(smem_addr(&sm[OFF_BL + buf * B_BUF + k * B_STR + b_n8]),
                       g_w1l + off, 16);
        }
        CP_COMMIT();
    };
    auto load_A = [&](int kt) {
#pragma unroll
        for (int i = 0; i < 2; i++) {
            int gr = rowBase + a_r0 + i * 32;
            stA[i] = make_float4(0.f, 0.f, 0.f, 0.f);
            if (gr < N_NODES)
                stA[i] = *(const float4*)(X + (size_t)gr * F_IN + kt + a_c4);
        }
    };
    auto store_A = [&](int buf) {
#pragma unroll
        for (int i = 0; i < 2; i++) {
            int r = a_r0 + i * 32;
            float4 v = stA[i];
            uint2 u;
            *(__half2*)&u.x = __floats2half2_rn(v.x, v.y);
            *(__half2*)&u.y = __floats2half2_rn(v.z, v.w);
            *(uint2*)&sm[OFF_A + buf * A_BUF + r * A_STR + a_c4] = u;
        }
    };

    issue_B(0, 0);
    load_A(0);
    store_A(0);
    CP_WAIT0();
    __syncthreads();

    for (int kc = 0; kc < NKC; kc++) {
        int buf = kc & 1;
        if (kc + 1 < NKC) {
            issue_B((kc + 1) * BK, buf ^ 1);
            load_A((kc + 1) * BK);
        }

#pragma unroll
        for (int ks = 0; ks < 2; ks++) {
            int k16 = ks * 16;
            uint32_t a[2][4], bh[4][2], bl[4][2];
#pragma unroll
            for (int mi = 0; mi < 2; mi++) {
                int row = wm * 32 + mi * 16 + (lane & 15);
                int col = k16 + (lane >> 4) * 8;
                LDSM_X4(a[mi], smem_addr(&sm[OFF_A + buf * A_BUF + row * A_STR + col]));
            }
#pragma unroll
            for (int ni = 0; ni < 4; ni++) {
                int krow = k16 + (lane & 15);
                int col  = wn * 32 + ni * 8;
                LDSM_X2T(bh[ni], smem_addr(&sm[OFF_BH + buf * B_BUF + krow * B_STR + col]));
                LDSM_X2T(bl[ni], smem_addr(&sm[OFF_BL + buf * B_BUF + krow * B_STR + col]));
            }
#pragma unroll
            for (int mi = 0; mi < 2; mi++)
#pragma unroll
                for (int ni = 0; ni < 4; ni++) {
                    MMA_F16(acc[mi][ni], a[mi], bh[ni]);
                    MMA_F16(acc[mi][ni], a[mi], bl[ni]);
                }
        }
        if (kc + 1 < NKC) store_A(buf ^ 1);
        CP_WAIT0();
        __syncthreads();
    }

    const int rBase = rowBase + wm * 32 + (lane >> 2);
    const int cBase = wn * 32 + (lane & 3) * 2;
#pragma unroll
    for (int mi = 0; mi < 2; mi++) {
        int gr0 = rBase + mi * 16;
        int gr1 = gr0 + 8;
#pragma unroll
        for (int ni = 0; ni < 4; ni++) {
            int gc = cBase + ni * 8;
            if (gr0 < N_NODES)
                *(__half2*)(g_q1h + (size_t)gr0 * HID + gc) =
                    __floats2half2_rn(acc[mi][ni][0], acc[mi][ni][1]);
            if (gr1 < N_NODES)
                *(__half2*)(g_q1h + (size_t)gr1 * HID + gc) =
                    __floats2half2_rn(acc[mi][ni][2], acc[mi][ni][3]);
        }
    }
}

// ---------------- CSR aggregation layer 1 (4-way MLP, round-13 form) --------
__global__ void k_agg1(const float* __restrict__ b1) {
    int node = blockIdx.x * (blockDim.x >> 5) + (threadIdx.x >> 5);
    int lane = threadIdx.x & 31;
    if (node >= N_NODES) return;
    int start = g_rowptr[node];
    int deg   = g_rowptr[node + 1] - start;
    float d = g_dinv[node];

    const uint2* q1v = (const uint2*)g_q1h;

    auto gacc = [&](int s, float ds, float4& a) {
        uint2 u = q1v[(size_t)s * 32 + lane];
        float2 p0 = __half22float2(*(__half2*)&u.x);
        float2 p1 = __half22float2(*(__half2*)&u.y);
        a.x += p0.x * ds; a.y += p0.y * ds;
        a.z += p1.x * ds; a.w += p1.y * ds;
    };

    float4 acc = make_float4(0.f, 0.f, 0.f, 0.f);
    gacc(node, d, acc);                          // self term

    int myidx = (lane < deg) ? g_col[start + lane] : 0;
    int n32 = deg < 32 ? deg : 32;
    int e = 0;
    for (; e + 4 <= n32; e += 4) {
        int s0 = __shfl_sync(0xffffffffu, myidx, e);
        int s1 = __shfl_sync(0xffffffffu, myidx, e + 1);
        int s2 = __shfl_sync(0xffffffffu, myidx, e + 2);
        int s3 = __shfl_sync(0xffffffffu, myidx, e + 3);
        float d0 = g_dinv[s0], d1 = g_dinv[s1], d2 = g_dinv[s2], d3 = g_dinv[s3];
        uint2 u0 = q1v[(size_t)s0 * 32 + lane];
        uint2 u1 = q1v[(size_t)s1 * 32 + lane];
        uint2 u2 = q1v[(size_t)s2 * 32 + lane];
        uint2 u3 = q1v[(size_t)s3 * 32 + lane];
        float2 a0 = __half22float2(*(__half2*)&u0.x), c0 = __half22float2(*(__half2*)&u0.y);
        float2 a1 = __half22float2(*(__half2*)&u1.x), c1 = __half22float2(*(__half2*)&u1.y);
        float2 a2 = __half22float2(*(__half2*)&u2.x), c2 = __half22float2(*(__half2*)&u2.y);
        float2 a3 = __half22float2(*(__half2*)&u3.x), c3 = __half22float2(*(__half2*)&u3.y);
        acc.x += (a0.x * d0 + a1.x * d1) + (a2.x * d2 + a3.x * d3);
        acc.y += (a0.y * d0 + a1.y * d1) + (a2.y * d2 + a3.y * d3);
        acc.z += (c0.x * d0 + c1.x * d1) + (c2.x * d2 + c3.x * d3);
        acc.w += (c0.y * d0 + c1.y * d1) + (c2.y * d2 + c3.y * d3);
    }
    for (; e < n32; e++) {
        int s = __shfl_sync(0xffffffffu, myidx, e);
        gacc(s, g_dinv[s], acc);
    }
    for (e = 32; e < deg; e++) {
        int s = g_col[start + e];
        gacc(s, g_dinv[s], acc);
    }

    float4 b = ((const float4*)b1)[lane];
    float4 o;
    o.x = fmaxf(fmaf(acc.x, d, b.x), 0.f);
    o.y = fmaxf(fmaf(acc.y, d, b.y), 0.f);
    o.z = fmaxf(fmaf(acc.z, d, b.z), 0.f);
    o.w = fmaxf(fmaf(acc.w, d, b.w), 0.f);
    uint2 u;
    *(__half2*)&u.x = __floats2half2_rn(o.x, o.y);
    *(__half2*)&u.y = __floats2half2_rn(o.z, o.w);
    ((uint2*)(g_h1h + (size_t)node * HID))[lane] = u;
}

// ---------------- layer-2 GEMM: fp16 A (h1 direct) + fp16-split W2, 2xMMA ---
// q2h = fp16((h1 @ W2) * dinv[row]);  M tile 128, N=32, K=128
#define A2_STR 40
#define B2_STR 40
__global__ __launch_bounds__(256, 2) void gemm2_mma() {
    __shared__ __align__(16) __half sA [128][A2_STR];
    __shared__ __align__(16) __half sBh[BK][B2_STR];
    __shared__ __align__(16) __half sBl[BK][B2_STR];

    const int tid  = threadIdx.x;
    const int lane = tid & 31;
    const int wid  = tid >> 5;
    const int rowBase = blockIdx.x * 128;

    float acc[4][4];
#pragma unroll
    for (int ni = 0; ni < 4; ni++)
#pragma unroll
        for (int r = 0; r < 4; r++) acc[ni][r] = 0.f;

    for (int kt = 0; kt < HID; kt += BK) {
        // A tile: h1h[rowBase..+128, kt..+32) via cp.async (512 16B chunks)
#pragma unroll
        for (int i = 0; i < 2; i++) {
            int idx = tid + i * 256;
            int r = idx >> 2, c8 = (idx & 3) * 8;
            int gr = rowBase + r;
            int ok = (gr < N_NODES);
            const __half* src = g_h1h + (size_t)(ok ? gr : 0) * HID + kt + c8;
            CP_ASYNC16(smem_addr(&sA[r][c8]), src, ok ? 16 : 0);
        }
        // B tiles: W2 hi (threads 0-127), lo (threads 128-255)
        {
            int t = tid & 127;
            int r = t >> 2, c8 = (t & 3) * 8;
            size_t off = (size_t)(kt + r) * CLS + c8;
            if (tid < 128) CP_ASYNC16(smem_addr(&sBh[r][c8]), g_w2h + off, 16);
            else           CP_ASYNC16(smem_addr(&sBl[r][c8]), g_w2l + off, 16);
        }
        CP_COMMIT();
        CP_WAIT0();
        __syncthreads();

#pragma unroll
        for (int ks = 0; ks < 2; ks++) {
            int k16 = ks * 16;
            uint32_t a[4], bh[4][2], bl[4][2];
            {
                int row = wid * 16 + (lane & 15);
                int col = k16 + (lane >> 4) * 8;
                LDSM_X4(a, smem_addr(&sA[row][col]));
            }
#pragma unroll
            for (int ni = 0; ni < 4; ni++) {
                int krow = k16 + (lane & 15);
                int col  = ni * 8;
                LDSM_X2T(bh[ni], smem_addr(&sBh[krow][col]));
                LDSM_X2T(bl[ni], smem_addr(&sBl[krow][col]));
            }
#pragma unroll
            for (int ni = 0; ni < 4; ni++) {
                MMA_F16(acc[ni], a, bh[ni]);
                MMA_F16(acc[ni], a, bl[ni]);
            }
        }
        __syncthreads();
    }

    const int r0 = rowBase + wid * 16 + (lane >> 2);
    const int r1 = r0 + 8;
    const int cBase = (lane & 3) * 2;
    float d0 = (r0 < N_NODES) ? g_dinv[r0] : 0.f;
    float d1 = (r1 < N_NODES) ? g_dinv[r1] : 0.f;
#pragma unroll
    for (int ni = 0; ni < 4; ni++) {
        int gc = cBase + ni * 8;
        if (r0 < N_NODES)
            *(__half2*)(g_q2h + (size_t)r0 * CLS + gc) =
                __floats2half2_rn(acc[ni][0] * d0, acc[ni][1] * d0);
        if (r1 < N_NODES)
            *(__half2*)(g_q2h + (size_t)r1 * CLS + gc) =
                __floats2half2_rn(acc[ni][2] * d1, acc[ni][3] * d1);
    }
}

// ---------------- CSR aggregation layer 2 (4-way MLP, bias+logsoftmax) ------
__global__ void k_agg2(const float* __restrict__ b2,
                       float* __restrict__ out) {
    int node = blockIdx.x * (blockDim.x >> 5) + (threadIdx.x >> 5);
    int lane = threadIdx.x & 31;
    if (node >= N_NODES) return;
    int start = g_rowptr[node];
    int deg   = g_rowptr[node + 1] - start;

    float acc = __half2float(g_q2h[(size_t)node * CLS + lane]);   // self term

    int myidx = (lane < deg) ? g_col[start + lane] : 0;
    int n32 = deg < 32 ? deg : 32;
    int e = 0;
    for (; e + 4 <= n32; e += 4) {
        int s0 = __shfl_sync(0xffffffffu, myidx, e);
        int s1 = __shfl_sync(0xffffffffu, myidx, e + 1);
        int s2 = __shfl_sync(0xffffffffu, myidx, e + 2);
        int s3 = __shfl_sync(0xffffffffu, myidx, e + 3);
        float v0 = __half2float(g_q2h[(size_t)s0 * CLS + lane]);
        float v1 = __half2float(g_q2h[(size_t)s1 * CLS + lane]);
        float v2 = __half2float(g_q2h[(size_t)s2 * CLS + lane]);
        float v3 = __half2float(g_q2h[(size_t)s3 * CLS + lane]);
        acc += (v0 + v1) + (v2 + v3);
    }
    for (; e < n32; e++) {
        int s = __shfl_sync(0xffffffffu, myidx, e);
        acc += __half2float(g_q2h[(size_t)s * CLS + lane]);
    }
    for (e = 32; e < deg; e++)
        acc += __half2float(g_q2h[(size_t)g_col[start + e] * CLS + lane]);

    float v = fmaf(acc, g_dinv[node], b2[lane]);
    float m = v;
#pragma unroll
    for (int o = 16; o > 0; o >>= 1) m = fmaxf(m, __shfl_xor_sync(0xffffffffu, m, o));
    float ex = __expf(v - m);
    float ssum = ex;
#pragma unroll
    for (int o = 16; o > 0; o >>= 1) ssum += __shfl_xor_sync(0xffffffffu, ssum, o);
    out[(size_t)node * CLS + lane] = v - m - __logf(ssum);
}

// ---------------- launch -----------------------------------------------------
extern "C" void kernel_launch(void* const* d_in, const int* in_sizes, int n_in,
                              void* d_out, int out_size) {
    const float* X   = (const float*)d_in[0];
    const int*   ei  = (const int*)d_in[1];
    const float* W1  = (const float*)d_in[2];
    const float* b1  = (const float*)d_in[3];
    const float* W2  = (const float*)d_in[4];
    const float* b2  = (const float*)d_in[5];
    float*       out = (float*)d_out;

    cudaFuncSetAttribute(gemm1_mma, cudaFuncAttributeMaxDynamicSharedMemorySize,
                         SMEM_G1_BYTES);

    const int TB = 256;
    const int nodeGrid = (N_NODES + TB - 1) / TB;
    const int edgeGrid = (N_EDGES + TB - 1) / TB;
    const bool fork = g_s2 && g_e0 && g_e2;

    // fused init: W1/W2 conversion + cnt zero + dtype probe (one launch)
    k_init<<<nodeGrid, TB>>>(W1, W2, ei);

    // fork: GEMM1 on side stream — independent of the degree chain
    if (fork) {
        cudaEventRecord(g_e0, 0);
        cudaStreamWaitEvent(g_s2, g_e0, 0);
        gemm1_mma<<<(N_NODES + BM - 1) / BM, 256, SMEM_G1_BYTES, g_s2>>>(X);
        cudaEventRecord(g_e2, g_s2);
    } else {
        gemm1_mma<<<(N_NODES + BM - 1) / BM, 256, SMEM_G1_BYTES>>>(X);
    }

    // degree + CSR chain on main stream (hidden under gemm1)
    k_cnt_scatter<<<edgeGrid, TB>>>(ei);
    k_scan1      <<<N_SBLK, SCAN_B>>>();
    k_scan2      <<<1, 256>>>();
    k_scan3      <<<nodeGrid, TB>>>();
    k_fill       <<<edgeGrid, TB>>>(ei);

    if (fork) cudaStreamWaitEvent(0, g_e2, 0);   // join before agg1

    k_agg1   <<<(N_NODES * 32 + TB - 1) / TB, TB>>>(b1);
    gemm2_mma<<<(N_NODES + 127) / 128, 256>>>();
    k_agg2   <<<(N_NODES * 32 + TB - 1) / TB, TB>>>(b2, out);
}

// round 17
// speedup vs baseline: 1.3942x; 1.3942x over previous
#include <cuda_runtime.h>
#include <cuda_fp16.h>
#include <cstdint>

#define N_NODES 100000
#define N_EDGES 800000
#define F_IN    256
#define HID     128
#define CLS     32
#define SCAN_B  512
#define N_SBLK  ((N_NODES + SCAN_B - 1) / SCAN_B)   // 196

// ---------------- scratch (device globals: no allocation allowed) ----------
__device__ int    g_cnt[N_NODES];
__device__ float  g_dinv[N_NODES];
__device__ int    g_rowptr[N_NODES + 1];
__device__ int    g_cursor[N_NODES];
__device__ int    g_col[N_EDGES];
__device__ int    g_bsum[N_SBLK];
__device__ int    g_boff[N_SBLK];
__device__ __half g_q1h[(size_t)N_NODES * HID];   // raw xw1, fp16
__device__ __half g_h1h[(size_t)N_NODES * HID];   // relu output, fp16
__device__ __half g_q2h[(size_t)N_NODES * CLS];   // xw2*dinv, fp16
__device__ __half g_w1h[F_IN * HID];              // W1 fp16 hi
__device__ __half g_w1l[F_IN * HID];              // W1 fp16 lo
__device__ __half g_w2h[HID * CLS];
__device__ __half g_w2l[HID * CLS];
__device__ int    g_is64;

// ---------------- stream/events for fork-join overlap (created at load) -----
static cudaStream_t g_s2 = nullptr;
static cudaEvent_t  g_e0 = nullptr, g_e2 = nullptr;
namespace {
struct HxStreamInit {
    HxStreamInit() {
        cudaStreamCreateWithFlags(&g_s2, cudaStreamNonBlocking);
        cudaEventCreateWithFlags(&g_e0, cudaEventDisableTiming);
        cudaEventCreateWithFlags(&g_e2, cudaEventDisableTiming);
    }
};
static HxStreamInit g_hx_stream_init;
}

// ---------------- helpers ----------------------------------------------------
__device__ __forceinline__ uint32_t smem_addr(const void* p) {
    return (uint32_t)__cvta_generic_to_shared(p);
}
#define LDSM_X4(r, a)                                                          \
    asm volatile("ldmatrix.sync.aligned.m8n8.x4.shared.b16 {%0,%1,%2,%3}, [%4];" \
                 : "=r"((r)[0]), "=r"((r)[1]), "=r"((r)[2]), "=r"((r)[3])      \
                 : "r"(a))
#define LDSM_X2T(r, a)                                                         \
    asm volatile("ldmatrix.sync.aligned.m8n8.x2.trans.shared.b16 {%0,%1}, [%2];" \
                 : "=r"((r)[0]), "=r"((r)[1]) : "r"(a))
#define MMA_F16(c, a, b)                                                       \
    asm volatile("mma.sync.aligned.m16n8k16.row.col.f32.f16.f16.f32 "          \
                 "{%0,%1,%2,%3}, {%4,%5,%6,%7}, {%8,%9}, {%0,%1,%2,%3};"       \
                 : "+f"((c)[0]), "+f"((c)[1]), "+f"((c)[2]), "+f"((c)[3])      \
                 : "r"((a)[0]), "r"((a)[1]), "r"((a)[2]), "r"((a)[3]),         \
                   "r"((b)[0]), "r"((b)[1]))
#define CP_ASYNC16(dst, src, sz)                                               \
    asm volatile("cp.async.ca.shared.global [%0], [%1], 16, %2;"               \
                 :: "r"(dst), "l"(src), "r"(sz) : "memory")
#define CP_COMMIT() asm volatile("cp.async.commit_group;" ::: "memory")
#define CP_WAIT0()  asm volatile("cp.async.wait_group 0;" ::: "memory")

__device__ __forceinline__ int edge_at(const int* __restrict__ ei,
                                       int which, int e, int is64) {
    size_t base = (size_t)which * N_EDGES + (size_t)e;
    return is64 ? ei[base * 2] : ei[base];
}

// ---------------- weight conversion (hi/lo fp16 split) ----------------------
__global__ void k_convw(const float* __restrict__ W1,
                        const float* __restrict__ W2) {
    int i = blockIdx.x * blockDim.x + threadIdx.x;
    if (i < F_IN * HID) {
        float x = W1[i];
        __half h = __float2half_rn(x);
        g_w1h[i] = h;
        g_w1l[i] = __float2half_rn(x - __half2float(h));
    }
    if (i < HID * CLS) {
        float x = W2[i];
        __half h = __float2half_rn(x);
        g_w2h[i] = h;
        g_w2l[i] = __float2half_rn(x - __half2float(h));
    }
}

// ---------------- degree count (+ dtype probe fused) ------------------------
__global__ void k_zero_cnt(const int* __restrict__ ei) {
    int i = blockIdx.x * blockDim.x + threadIdx.x;
    if (i < N_NODES) g_cnt[i] = 0;
    if (i == 0) {
        int is64 = 1;
        for (int j = 0; j < 64; j++)
            if (ei[2 * j + 1] != 0) { is64 = 0; break; }
        g_is64 = is64;
    }
}
__global__ void k_cnt_scatter(const int* __restrict__ ei) {
    int e = blockIdx.x * blockDim.x + threadIdx.x;
    if (e >= N_EDGES) return;
    atomicAdd(&g_cnt[edge_at(ei, 1, e, g_is64)], 1);
}

// ---------------- CSR build: 3-phase scan (+dinv fused) + fill --------------
__global__ void k_scan1() {
    __shared__ int sh[SCAN_B];
    int t = threadIdx.x;
    int i = blockIdx.x * SCAN_B + t;
    int v = (i < N_NODES) ? g_cnt[i] : 0;
    sh[t] = v;
    __syncthreads();
#pragma unroll
    for (int off = 1; off < SCAN_B; off <<= 1) {
        int x = (t >= off) ? sh[t - off] : 0;
        __syncthreads();
        sh[t] += x;
        __syncthreads();
    }
    if (i < N_NODES) g_rowptr[i] = sh[t] - v;
    if (t == SCAN_B - 1) g_bsum[blockIdx.x] = sh[t];
}
__global__ void k_scan2() {
    __shared__ int sh[256];
    int t = threadIdx.x;
    int v = (t < N_SBLK) ? g_bsum[t] : 0;
    sh[t] = v;
    __syncthreads();
#pragma unroll
    for (int off = 1; off < 256; off <<= 1) {
        int x = (t >= off) ? sh[t - off] : 0;
        __syncthreads();
        sh[t] += x;
        __syncthreads();
    }
    if (t < N_SBLK) g_boff[t] = sh[t] - v;
}
__global__ void k_scan3() {
    int i = blockIdx.x * blockDim.x + threadIdx.x;
    if (i < N_NODES) {
        int rp = g_rowptr[i] + g_boff[i / SCAN_B];
        g_rowptr[i] = rp;
        g_cursor[i] = rp;
        g_dinv[i]   = rsqrtf((float)(g_cnt[i] + 1));   // +1 self loop
    }
    if (i == 0) g_rowptr[N_NODES] = N_EDGES;
}
__global__ void k_fill(const int* __restrict__ ei) {
    int e = blockIdx.x * blockDim.x + threadIdx.x;
    if (e >= N_EDGES) return;
    int is64 = g_is64;
    int s = edge_at(ei, 0, e, is64);
    int d = edge_at(ei, 1, e, is64);
    int pos = atomicAdd(&g_cursor[d], 1);
    g_col[pos] = s;
}

// ---------------- layer-1 GEMM: fp16 A + fp16-split W1, 2xMMA, cp.async -----
// q1h = fp16(X @ W1)
#define BM 64
#define BK 32
#define NKC (F_IN / BK)        // 8
#define A_STR 40               // halves
#define B_STR 136
#define A_BUF (BM * A_STR)     // 2560
#define B_BUF (BK * B_STR)     // 4352
#define OFF_A  0
#define OFF_BH (2 * A_BUF)
#define OFF_BL (2 * A_BUF + 2 * B_BUF)
#define SMEM_G1_ELEMS (2 * A_BUF + 4 * B_BUF)   // 22528 halves
#define SMEM_G1_BYTES (SMEM_G1_ELEMS * 2)       // 45056 B

__global__ __launch_bounds__(256, 2) void gemm1_mma(const float* __restrict__ X) {
    extern __shared__ __align__(16) char dsm_raw[];
    __half* sm = (__half*)dsm_raw;

    const int tid  = threadIdx.x;
    const int lane = tid & 31;
    const int wid  = tid >> 5;
    const int wm   = wid >> 2;       // 0..1 (32 rows)
    const int wn   = wid & 3;        // 0..3 (32 cols)
    const int rowBase = blockIdx.x * BM;

    const int a_r0 = tid >> 3,  a_c4 = (tid & 7) * 4;
    const int b_k0 = tid >> 4,  b_n8 = (tid & 15) * 8;

    float4 stA[2];

    float acc[2][4][4];
#pragma unroll
    for (int mi = 0; mi < 2; mi++)
#pragma unroll
        for (int ni = 0; ni < 4; ni++)
#pragma unroll
            for (int r = 0; r < 4; r++) acc[mi][ni][r] = 0.f;

    auto issue_B = [&](int kt, int buf) {
#pragma unroll
        for (int i = 0; i < 2; i++) {
            int k = b_k0 + i * 16;
            size_t off = (size_t)(kt + k) * HID + b_n8;
            CP_ASYNC16(smem_addr(&sm[OFF_BH + buf * B_BUF + k * B_STR + b_n8]),
                       g_w1h + off, 16);
            CP_ASYNC16(smem_addr(&sm[OFF_BL + buf * B_BUF + k * B_STR + b_n8]),
                       g_w1l + off, 16);
        }
        CP_COMMIT();
    };
    auto load_A = [&](int kt) {
#pragma unroll
        for (int i = 0; i < 2; i++) {
            int gr = rowBase + a_r0 + i * 32;
            stA[i] = make_float4(0.f, 0.f, 0.f, 0.f);
            if (gr < N_NODES)
                stA[i] = *(const float4*)(X + (size_t)gr * F_IN + kt + a_c4);
        }
    };
    auto store_A = [&](int buf) {
#pragma unroll
        for (int i = 0; i < 2; i++) {
            int r = a_r0 + i * 32;
            float4 v = stA[i];
            uint2 u;
            *(__half2*)&u.x = __floats2half2_rn(v.x, v.y);
            *(__half2*)&u.y = __floats2half2_rn(v.z, v.w);
            *(uint2*)&sm[OFF_A + buf * A_BUF + r * A_STR + a_c4] = u;
        }
    };

    issue_B(0, 0);
    load_A(0);
    store_A(0);
    CP_WAIT0();
    __syncthreads();

    for (int kc = 0; kc < NKC; kc++) {
        int buf = kc & 1;
        if (kc + 1 < NKC) {
            issue_B((kc + 1) * BK, buf ^ 1);
            load_A((kc + 1) * BK);
        }

#pragma unroll
        for (int ks = 0; ks < 2; ks++) {
            int k16 = ks * 16;
            uint32_t a[2][4], bh[4][2], bl[4][2];
#pragma unroll
            for (int mi = 0; mi < 2; mi++) {
                int row = wm * 32 + mi * 16 + (lane & 15);
                int col = k16 + (lane >> 4) * 8;
                LDSM_X4(a[mi], smem_addr(&sm[OFF_A + buf * A_BUF + row * A_STR + col]));
            }
#pragma unroll
            for (int ni = 0; ni < 4; ni++) {
                int krow = k16 + (lane & 15);
                int col  = wn * 32 + ni * 8;
                LDSM_X2T(bh[ni], smem_addr(&sm[OFF_BH + buf * B_BUF + krow * B_STR + col]));
                LDSM_X2T(bl[ni], smem_addr(&sm[OFF_BL + buf * B_BUF + krow * B_STR + col]));
            }
#pragma unroll
            for (int mi = 0; mi < 2; mi++)
#pragma unroll
                for (int ni = 0; ni < 4; ni++) {
                    MMA_F16(acc[mi][ni], a[mi], bh[ni]);
                    MMA_F16(acc[mi][ni], a[mi], bl[ni]);
                }
        }
        if (kc + 1 < NKC) store_A(buf ^ 1);
        CP_WAIT0();
        __syncthreads();
    }

    const int rBase = rowBase + wm * 32 + (lane >> 2);
    const int cBase = wn * 32 + (lane & 3) * 2;
#pragma unroll
    for (int mi = 0; mi < 2; mi++) {
        int gr0 = rBase + mi * 16;
        int gr1 = gr0 + 8;
#pragma unroll
        for (int ni = 0; ni < 4; ni++) {
            int gc = cBase + ni * 8;
            if (gr0 < N_NODES)
                *(__half2*)(g_q1h + (size_t)gr0 * HID + gc) =
                    __floats2half2_rn(acc[mi][ni][0], acc[mi][ni][1]);
            if (gr1 < N_NODES)
                *(__half2*)(g_q1h + (size_t)gr1 * HID + gc) =
                    __floats2half2_rn(acc[mi][ni][2], acc[mi][ni][3]);
        }
    }
}

// ---------------- CSR aggregation layer 1 (fp16 gather, fp16 h1 write) ------
__global__ void k_agg1(const float* __restrict__ b1) {
    int node = blockIdx.x * (blockDim.x >> 5) + (threadIdx.x >> 5);
    int lane = threadIdx.x & 31;
    if (node >= N_NODES) return;
    int start = g_rowptr[node];
    int deg   = g_rowptr[node + 1] - start;
    float d = g_dinv[node];

    const uint2* q1v = (const uint2*)g_q1h;

    auto gacc = [&](int s, float ds, float4& a) {
        uint2 u = q1v[(size_t)s * 32 + lane];
        float2 p0 = __half22float2(*(__half2*)&u.x);
        float2 p1 = __half22float2(*(__half2*)&u.y);
        a.x += p0.x * ds; a.y += p0.y * ds;
        a.z += p1.x * ds; a.w += p1.y * ds;
    };

    float4 acc = make_float4(0.f, 0.f, 0.f, 0.f);
    gacc(node, d, acc);                          // self term

    int myidx = (lane < deg) ? g_col[start + lane] : 0;
    int n32 = deg < 32 ? deg : 32;
    int e = 0;
    for (; e + 4 <= n32; e += 4) {
        int s0 = __shfl_sync(0xffffffffu, myidx, e);
        int s1 = __shfl_sync(0xffffffffu, myidx, e + 1);
        int s2 = __shfl_sync(0xffffffffu, myidx, e + 2);
        int s3 = __shfl_sync(0xffffffffu, myidx, e + 3);
        float d0 = g_dinv[s0], d1 = g_dinv[s1], d2 = g_dinv[s2], d3 = g_dinv[s3];
        uint2 u0 = q1v[(size_t)s0 * 32 + lane];
        uint2 u1 = q1v[(size_t)s1 * 32 + lane];
        uint2 u2 = q1v[(size_t)s2 * 32 + lane];
        uint2 u3 = q1v[(size_t)s3 * 32 + lane];
        float2 a0 = __half22float2(*(__half2*)&u0.x), c0 = __half22float2(*(__half2*)&u0.y);
        float2 a1 = __half22float2(*(__half2*)&u1.x), c1 = __half22float2(*(__half2*)&u1.y);
        float2 a2 = __half22float2(*(__half2*)&u2.x), c2 = __half22float2(*(__half2*)&u2.y);
        float2 a3 = __half22float2(*(__half2*)&u3.x), c3 = __half22float2(*(__half2*)&u3.y);
        acc.x += (a0.x * d0 + a1.x * d1) + (a2.x * d2 + a3.x * d3);
        acc.y += (a0.y * d0 + a1.y * d1) + (a2.y * d2 + a3.y * d3);
        acc.z += (c0.x * d0 + c1.x * d1) + (c2.x * d2 + c3.x * d3);
        acc.w += (c0.y * d0 + c1.y * d1) + (c2.y * d2 + c3.y * d3);
    }
    for (; e < n32; e++) {
        int s = __shfl_sync(0xffffffffu, myidx, e);
        gacc(s, g_dinv[s], acc);
    }
    for (e = 32; e < deg; e++) {
        int s = g_col[start + e];
        gacc(s, g_dinv[s], acc);
    }

    float4 b = ((const float4*)b1)[lane];
    float4 o;
    o.x = fmaxf(fmaf(acc.x, d, b.x), 0.f);
    o.y = fmaxf(fmaf(acc.y, d, b.y), 0.f);
    o.z = fmaxf(fmaf(acc.z, d, b.z), 0.f);
    o.w = fmaxf(fmaf(acc.w, d, b.w), 0.f);
    uint2 u;
    *(__half2*)&u.x = __floats2half2_rn(o.x, o.y);
    *(__half2*)&u.y = __floats2half2_rn(o.z, o.w);
    ((uint2*)(g_h1h + (size_t)node * HID))[lane] = u;
}

// ---------------- layer-2 GEMM: fp16 A (h1 direct) + fp16-split W2, 2xMMA ---
// q2h = fp16((h1 @ W2) * dinv[row]);  M tile 128, N=32, K=128
#define A2_STR 40
#define B2_STR 40
__global__ __launch_bounds__(256, 2) void gemm2_mma() {
    __shared__ __align__(16) __half sA [128][A2_STR];
    __shared__ __align__(16) __half sBh[BK][B2_STR];
    __shared__ __align__(16) __half sBl[BK][B2_STR];

    const int tid  = threadIdx.x;
    const int lane = tid & 31;
    const int wid  = tid >> 5;
    const int rowBase = blockIdx.x * 128;

    float acc[4][4];
#pragma unroll
    for (int ni = 0; ni < 4; ni++)
#pragma unroll
        for (int r = 0; r < 4; r++) acc[ni][r] = 0.f;

    for (int kt = 0; kt < HID; kt += BK) {
        // A tile: h1h[rowBase..+128, kt..+32) via cp.async (512 16B chunks)
#pragma unroll
        for (int i = 0; i < 2; i++) {
            int idx = tid + i * 256;
            int r = idx >> 2, c8 = (idx & 3) * 8;
            int gr = rowBase + r;
            int ok = (gr < N_NODES);
            const __half* src = g_h1h + (size_t)(ok ? gr : 0) * HID + kt + c8;
            CP_ASYNC16(smem_addr(&sA[r][c8]), src, ok ? 16 : 0);
        }
        // B tiles: W2 hi (threads 0-127), lo (threads 128-255)
        {
            int t = tid & 127;
            int r = t >> 2, c8 = (t & 3) * 8;
            size_t off = (size_t)(kt + r) * CLS + c8;
            if (tid < 128) CP_ASYNC16(smem_addr(&sBh[r][c8]), g_w2h + off, 16);
            else           CP_ASYNC16(smem_addr(&sBl[r][c8]), g_w2l + off, 16);
        }
        CP_COMMIT();
        CP_WAIT0();
        __syncthreads();

#pragma unroll
        for (int ks = 0; ks < 2; ks++) {
            int k16 = ks * 16;
            uint32_t a[4], bh[4][2], bl[4][2];
            {
                int row = wid * 16 + (lane & 15);
                int col = k16 + (lane >> 4) * 8;
                LDSM_X4(a, smem_addr(&sA[row][col]));
            }
#pragma unroll
            for (int ni = 0; ni < 4; ni++) {
                int krow = k16 + (lane & 15);
                int col  = ni * 8;
                LDSM_X2T(bh[ni], smem_addr(&sBh[krow][col]));
                LDSM_X2T(bl[ni], smem_addr(&sBl[krow][col]));
            }
#pragma unroll
            for (int ni = 0; ni < 4; ni++) {
                MMA_F16(acc[ni], a, bh[ni]);
                MMA_F16(acc[ni], a, bl[ni]);
            }
        }
        __syncthreads();
    }

    const int r0 = rowBase + wid * 16 + (lane >> 2);
    const int r1 = r0 + 8;
    const int cBase = (lane & 3) * 2;
    float d0 = (r0 < N_NODES) ? g_dinv[r0] : 0.f;
    float d1 = (r1 < N_NODES) ? g_dinv[r1] : 0.f;
#pragma unroll
    for (int ni = 0; ni < 4; ni++) {
        int gc = cBase + ni * 8;
        if (r0 < N_NODES)
            *(__half2*)(g_q2h + (size_t)r0 * CLS + gc) =
                __floats2half2_rn(acc[ni][0] * d0, acc[ni][1] * d0);
        if (r1 < N_NODES)
            *(__half2*)(g_q2h + (size_t)r1 * CLS + gc) =
                __floats2half2_rn(acc[ni][2] * d1, acc[ni][3] * d1);
    }
}

// ---------------- CSR aggregation layer 2 (fp16 gather, bias+logsoftmax) ----
__global__ void k_agg2(const float* __restrict__ b2,
                       float* __restrict__ out) {
    int node = blockIdx.x * (blockDim.x >> 5) + (threadIdx.x >> 5);
    int lane = threadIdx.x & 31;
    if (node >= N_NODES) return;
    int start = g_rowptr[node];
    int deg   = g_rowptr[node + 1] - start;

    float acc = __half2float(g_q2h[(size_t)node * CLS + lane]);   // self term

    int myidx = (lane < deg) ? g_col[start + lane] : 0;
    int n32 = deg < 32 ? deg : 32;
    int e = 0;
    for (; e + 4 <= n32; e += 4) {
        int s0 = __shfl_sync(0xffffffffu, myidx, e);
        int s1 = __shfl_sync(0xffffffffu, myidx, e + 1);
        int s2 = __shfl_sync(0xffffffffu, myidx, e + 2);
        int s3 = __shfl_sync(0xffffffffu, myidx, e + 3);
        float v0 = __half2float(g_q2h[(size_t)s0 * CLS + lane]);
        float v1 = __half2float(g_q2h[(size_t)s1 * CLS + lane]);
        float v2 = __half2float(g_q2h[(size_t)s2 * CLS + lane]);
        float v3 = __half2float(g_q2h[(size_t)s3 * CLS + lane]);
        acc += (v0 + v1) + (v2 + v3);
    }
    for (; e < n32; e++) {
        int s = __shfl_sync(0xffffffffu, myidx, e);
        acc += __half2float(g_q2h[(size_t)s * CLS + lane]);
    }
    for (e = 32; e < deg; e++)
        acc += __half2float(g_q2h[(size_t)g_col[start + e] * CLS + lane]);

    float v = fmaf(acc, g_dinv[node], b2[lane]);
    float m = v;
#pragma unroll
    for (int o = 16; o > 0; o >>= 1) m = fmaxf(m, __shfl_xor_sync(0xffffffffu, m, o));
    float ex = __expf(v - m);
    float ssum = ex;
#pragma unroll
    for (int o = 16; o > 0; o >>= 1) ssum += __shfl_xor_sync(0xffffffffu, ssum, o);
    out[(size_t)node * CLS + lane] = v - m - __logf(ssum);
}

// ---------------- launch -----------------------------------------------------
extern "C" void kernel_launch(void* const* d_in, const int* in_sizes, int n_in,
                              void* d_out, int out_size) {
    const float* X   = (const float*)d_in[0];
    const int*   ei  = (const int*)d_in[1];
    const float* W1  = (const float*)d_in[2];
    const float* b1  = (const float*)d_in[3];
    const float* W2  = (const float*)d_in[4];
    const float* b2  = (const float*)d_in[5];
    float*       out = (float*)d_out;

    cudaFuncSetAttribute(gemm1_mma, cudaFuncAttributeMaxDynamicSharedMemorySize,
                         SMEM_G1_BYTES);

    const int TB = 256;
    const int nodeGrid = (N_NODES + TB - 1) / TB;
    const int edgeGrid = (N_EDGES + TB - 1) / TB;
    const int convGrid = (F_IN * HID + TB - 1) / TB;
    const bool fork = g_s2 && g_e0 && g_e2;

    k_convw<<<convGrid, TB>>>(W1, W2);

    // fork: GEMM1 on side stream — independent of the degree chain
    if (fork) {
        cudaEventRecord(g_e0, 0);
        cudaStreamWaitEvent(g_s2, g_e0, 0);
        gemm1_mma<<<(N_NODES + BM - 1) / BM, 256, SMEM_G1_BYTES, g_s2>>>(X);
        cudaEventRecord(g_e2, g_s2);
    } else {
        gemm1_mma<<<(N_NODES + BM - 1) / BM, 256, SMEM_G1_BYTES>>>(X);
    }

    // degree + CSR chain on main stream (hidden under gemm1)
    k_zero_cnt   <<<nodeGrid, TB>>>(ei);
    k_cnt_scatter<<<edgeGrid, TB>>>(ei);
    k_scan1      <<<N_SBLK, SCAN_B>>>();
    k_scan2      <<<1, 256>>>();
    k_scan3      <<<nodeGrid, TB>>>();
    k_fill       <<<edgeGrid, TB>>>(ei);

    if (fork) cudaStreamWaitEvent(0, g_e2, 0);   // join before agg1

    k_agg1   <<<(N_NODES * 32 + TB - 1) / TB, TB>>>(b1);
    gemm2_mma<<<(N_NODES + 127) / 128, 256>>>();
    k_agg2   <<<(N_NODES * 32 + TB - 1) / TB, TB>>>(b2, out);
}